// round 13
// baseline (speedup 1.0000x reference)
#include <cuda_runtime.h>
#include <cuda_bf16.h>
#include <math.h>

// Problem constants
#define TSEQ 128
#define HU   64
#define NG   256
#define BATCH 2048
#define MTOT (BATCH*TSEQ)

typedef unsigned long long u64;
typedef unsigned int u32;

// Scratch (__device__ globals)
__device__ float g_xz[(size_t)MTOT * NG];                 // xz buffer (both layers)
__device__ __nv_bfloat16 g_ahi[(size_t)MTOT * 128];       // split-A hi (x, then h1)
__device__ __nv_bfloat16 g_alo[(size_t)MTOT * 128];       // split-A lo
__device__ __nv_bfloat16 g_whi[128 * NG];                 // split-W hi
__device__ __nv_bfloat16 g_wlo[128 * NG];                 // split-W lo

// ---------------------------------------------------------------------------
// Activation helpers
// ---------------------------------------------------------------------------
__device__ __forceinline__ float tanh_ap(float x) {
    float y; asm("tanh.approx.f32 %0, %1;" : "=f"(y) : "f"(x)); return y;
}
__device__ __forceinline__ float sig_ap(float x) {
    return fmaf(0.5f, tanh_ap(0.5f * x), 0.5f);
}

// ---------------------------------------------------------------------------
// mma.sync / ldmatrix helpers
// ---------------------------------------------------------------------------
__device__ __forceinline__ u32 smem_u32(const void* p) {
    u32 a;
    asm("{ .reg .u64 t; cvta.to.shared.u64 t, %1; cvt.u32.u64 %0, t; }"
        : "=r"(a) : "l"(p));
    return a;
}
__device__ __forceinline__ void ldsm4(u32 r[4], u32 addr) {
    asm volatile("ldmatrix.sync.aligned.m8n8.x4.shared.b16 {%0,%1,%2,%3}, [%4];"
                 : "=r"(r[0]), "=r"(r[1]), "=r"(r[2]), "=r"(r[3]) : "r"(addr));
}
__device__ __forceinline__ void ldsm4t(u32 r[4], u32 addr) {
    asm volatile("ldmatrix.sync.aligned.m8n8.x4.trans.shared.b16 {%0,%1,%2,%3}, [%4];"
                 : "=r"(r[0]), "=r"(r[1]), "=r"(r[2]), "=r"(r[3]) : "r"(addr));
}
__device__ __forceinline__ void ldsm2t(u32 r[2], u32 addr) {
    asm volatile("ldmatrix.sync.aligned.m8n8.x2.trans.shared.b16 {%0,%1}, [%2];"
                 : "=r"(r[0]), "=r"(r[1]) : "r"(addr));
}
__device__ __forceinline__ void mma16816(float d[4], const u32 a[4], const u32 b[2]) {
    asm volatile(
        "mma.sync.aligned.m16n8k16.row.col.f32.bf16.bf16.f32 "
        "{%0,%1,%2,%3}, {%4,%5,%6,%7}, {%8,%9}, {%0,%1,%2,%3};"
        : "+f"(d[0]), "+f"(d[1]), "+f"(d[2]), "+f"(d[3])
        : "r"(a[0]), "r"(a[1]), "r"(a[2]), "r"(a[3]), "r"(b[0]), "r"(b[1]));
}
// pack two fp32 -> bf16x2 (first arg in lower half)
__device__ __forceinline__ u32 cvt2bf(float lo, float hi) {
    u32 r; asm("cvt.rn.bf16x2.f32 %0, %1, %2;" : "=r"(r) : "f"(hi), "f"(lo));
    return r;
}

// ---------------------------------------------------------------------------
// Streaming split-convert: fp32[n4*4] -> bf16 hi[n4*4], lo[n4*4]
// ---------------------------------------------------------------------------
__global__ __launch_bounds__(256) void conv_split_kernel(
    const float* __restrict__ src,
    __nv_bfloat16* __restrict__ hi, __nv_bfloat16* __restrict__ lo, int n4)
{
    int idx = blockIdx.x * 256 + threadIdx.x;
    int stride = gridDim.x * 256;
    for (; idx < n4; idx += stride) {
        float4 v = ((const float4*)src)[idx];
        __nv_bfloat16 h0 = __float2bfloat16(v.x);
        __nv_bfloat16 h1 = __float2bfloat16(v.y);
        __nv_bfloat16 h2 = __float2bfloat16(v.z);
        __nv_bfloat16 h3 = __float2bfloat16(v.w);
        u32 hp0 = ((u32)__bfloat16_as_ushort(h1) << 16) | __bfloat16_as_ushort(h0);
        u32 hp1 = ((u32)__bfloat16_as_ushort(h3) << 16) | __bfloat16_as_ushort(h2);
        u32 lp0 = cvt2bf(v.x - __bfloat162float(h0), v.y - __bfloat162float(h1));
        u32 lp1 = cvt2bf(v.z - __bfloat162float(h2), v.w - __bfloat162float(h3));
        ((u64*)hi)[idx] = ((u64)hp1 << 32) | hp0;
        ((u64*)lo)[idx] = ((u64)lp1 << 32) | lp0;
    }
}

// ---------------------------------------------------------------------------
// Tensor-core GEMM (HMMA) v3: pre-converted bf16 inputs, staging = pure copy.
// C[M,256] = A[M,KF32] @ W[KF32,256] + bias, tile 128M x 128N, grid (M/128, 2),
// 70 KB smem -> 2 CTAs/SM.
// ---------------------------------------------------------------------------
#define A_PITCH 144
#define B_PITCH 272
#define S_AHI 0
#define S_ALO (128 * A_PITCH)                     // 18432
#define S_BHI (2 * 128 * A_PITCH)                 // 36864
#define S_BLO (2 * 128 * A_PITCH + 64 * B_PITCH)  // 54272
#define GEMM_SMEM (2 * 128 * A_PITCH + 2 * 64 * B_PITCH)  // 71680

template <int KF32>
__global__ __launch_bounds__(256, 2) void gemm_tc_kernel(
    const __nv_bfloat16* __restrict__ Ahi, const __nv_bfloat16* __restrict__ Alo,
    const __nv_bfloat16* __restrict__ Whi, const __nv_bfloat16* __restrict__ Wlo,
    const float* __restrict__ bias, float* __restrict__ C)
{
    extern __shared__ char smem[];
    const u32 sb = smem_u32(smem);

    const int tid = threadIdx.x;
    const int wid = tid >> 5;
    const int l   = tid & 31;
    const int m0  = blockIdx.x * 128;
    const int n0  = blockIdx.y * 128;
    const int wm  = (wid >> 2) * 64;
    const int wn  = (wid & 3) * 32;

    float acc[64];
#pragma unroll
    for (int i = 0; i < 64; i++) acc[i] = 0.f;

    const u32 aoff = (u32)((wm + (l & 7) + ((l >> 3) & 1) * 8) * A_PITCH + (l >> 4) * 16);
    const u32 boff = (u32)(((l & 7) + ((l >> 3) & 1) * 8) * B_PITCH + (wn + (l >> 4) * 8) * 2);

    const int NCHUNK = KF32 / 64;
    for (int kc = 0; kc < NCHUNK; kc++) {
        const int k0 = kc * 64;

        // ---- stage A chunk: copy [128][64] bf16 (hi & lo) ----
#pragma unroll
        for (int i = 0; i < 4; i++) {
            int idx = tid + i * 256;          // 0..1023
            int m = idx >> 3, q = idx & 7;    // 8 uint4 per 64-bf16 row
            size_t go = (size_t)(m0 + m) * KF32 + k0 + q * 8;
            u32 so = (u32)(m * A_PITCH + q * 16);
            *(uint4*)(smem + S_AHI + so) = *(const uint4*)(Ahi + go);
            *(uint4*)(smem + S_ALO + so) = *(const uint4*)(Alo + go);
        }
        // ---- stage B chunk: copy [64][128] bf16 (hi & lo) ----
#pragma unroll
        for (int i = 0; i < 4; i++) {
            int idx = tid + i * 256;          // 0..1023
            int k = idx >> 4, q = idx & 15;   // 16 uint4 per 128-bf16 row
            size_t go = (size_t)(k0 + k) * NG + n0 + q * 8;
            u32 so = (u32)(k * B_PITCH + q * 16);
            *(uint4*)(smem + S_BHI + so) = *(const uint4*)(Whi + go);
            *(uint4*)(smem + S_BLO + so) = *(const uint4*)(Wlo + go);
        }
        __syncthreads();

        // ---- MMA over 4 k16 steps: warp tile 64x32 ----
#pragma unroll
        for (int ks = 0; ks < 4; ks++) {
            u32 ahi[4][4], alo[4][4];
#pragma unroll
            for (int mt = 0; mt < 4; mt++) {
                u32 ao = aoff + (u32)(mt * 16 * A_PITCH + ks * 32);
                ldsm4(ahi[mt], sb + S_AHI + ao);
                ldsm4(alo[mt], sb + S_ALO + ao);
            }
#pragma unroll
            for (int ntp = 0; ntp < 2; ntp++) {
                u32 bo = boff + (u32)(ks * 16 * B_PITCH + ntp * 32);
                u32 bhi[4], blo[4];
                ldsm4t(bhi, sb + S_BHI + bo);
                ldsm4t(blo, sb + S_BLO + bo);
#pragma unroll
                for (int mt = 0; mt < 4; mt++) {
#pragma unroll
                    for (int h = 0; h < 2; h++) {
                        int nt = ntp * 2 + h;
                        float* d = &acc[(mt * 4 + nt) * 4];
                        mma16816(d, ahi[mt], &bhi[h * 2]);
                        mma16816(d, alo[mt], &bhi[h * 2]);
                        mma16816(d, ahi[mt], &blo[h * 2]);
                    }
                }
            }
        }
        __syncthreads();
    }

    // ---- epilogue: bias + store ----
#pragma unroll
    for (int mt = 0; mt < 4; mt++) {
        int r0 = m0 + wm + mt * 16 + (l >> 2);
#pragma unroll
        for (int nt = 0; nt < 4; nt++) {
            int col = n0 + wn + nt * 8 + 2 * (l & 3);
            float2 bv = *(const float2*)(bias + col);
            const float* d = &acc[(mt * 4 + nt) * 4];
            float2 o0 = make_float2(d[0] + bv.x, d[1] + bv.y);
            float2 o1 = make_float2(d[2] + bv.x, d[3] + bv.y);
            *(float2*)(C + (size_t)r0 * NG + col)       = o0;
            *(float2*)(C + (size_t)(r0 + 8) * NG + col) = o1;
        }
    }
}

// ---------------------------------------------------------------------------
// Tensor-core recurrent kernel.
// OUTBF=1: write h as bf16 hi/lo split (feeds next layer's GEMM directly).
// OUTBF=0: write h as fp32 (final output).
// ---------------------------------------------------------------------------
#define RB_PITCH 528
#define RS_UHI 0
#define RS_ULO 33792                 // 64*528
#define RS_H   67584                 // 2 bufs x (hi 2304 + lo 2304)
#define REC_SMEM (67584 + 9216)      // 76800

template <int ACT, int OUTBF>
__global__ __launch_bounds__(256, 1) void lstm_rec_mma(
    const float* __restrict__ xz, const float* __restrict__ U,
    float* __restrict__ hout,
    __nv_bfloat16* __restrict__ ohi, __nv_bfloat16* __restrict__ olo)
{
    extern __shared__ char smem[];
    const u32 sb = smem_u32(smem);

    const int tid = threadIdx.x;
    const int w   = tid >> 5;          // 0..7
    const int l   = tid & 31;
    const int b0  = blockIdx.x * 16;

    // ---- stage U (64x256 fp32) -> hi/lo bf16, pitch 528 ----
#pragma unroll
    for (int i = 0; i < 16; i++) {
        int idx = tid + i * 256;          // 0..4095
        int k = idx >> 6, nq = idx & 63;
        float4 v = *(const float4*)(U + (size_t)k * NG + nq * 4);
        __nv_bfloat16 h0 = __float2bfloat16(v.x);
        __nv_bfloat16 h1 = __float2bfloat16(v.y);
        __nv_bfloat16 h2 = __float2bfloat16(v.z);
        __nv_bfloat16 h3 = __float2bfloat16(v.w);
        u32 hp0 = ((u32)__bfloat16_as_ushort(h1) << 16) | __bfloat16_as_ushort(h0);
        u32 hp1 = ((u32)__bfloat16_as_ushort(h3) << 16) | __bfloat16_as_ushort(h2);
        u32 lp0 = cvt2bf(v.x - __bfloat162float(h0), v.y - __bfloat162float(h1));
        u32 lp1 = cvt2bf(v.z - __bfloat162float(h2), v.w - __bfloat162float(h3));
        u32 off = (u32)(k * RB_PITCH + nq * 8);
        *(u64*)(smem + RS_UHI + off) = ((u64)hp1 << 32) | hp0;
        *(u64*)(smem + RS_ULO + off) = ((u64)lp1 << 32) | lp0;
    }
    // zero both h buffers
#pragma unroll
    for (int i = 0; i < 9; i++)
        ((u32*)(smem + RS_H))[tid + i * 256] = 0;
    __syncthreads();

    // ---- preload B-fragments (U cols {8w..8w+7} + 64g) ----
    u32 bh[4][4][2], bl[4][4][2];
    {
        const u32 brow = (u32)((l & 7) + ((l >> 3) & 1) * 8);
#pragma unroll
        for (int g = 0; g < 4; g++)
#pragma unroll
            for (int ks = 0; ks < 4; ks++) {
                u32 off = (ks * 16 + brow) * RB_PITCH + (u32)(64 * g + 8 * w) * 2;
                ldsm2t(bh[g][ks], sb + RS_UHI + off);
                ldsm2t(bl[g][ks], sb + RS_ULO + off);
            }
    }

    const int r   = l >> 2;
    const int cq  = 2 * (l & 3);
    const int u0  = 8 * w + cq;
    float c[4];
#pragma unroll
    for (int i = 0; i < 4; i++) c[i] = 0.f;

    const float* pA = xz + (size_t)(b0 + r)     * TSEQ * NG;
    const float* pB = xz + (size_t)(b0 + r + 8) * TSEQ * NG;

    float xn[16];
#pragma unroll
    for (int g = 0; g < 4; g++) {
        int col = 64 * g + u0;
        float2 vA = *(const float2*)(pA + col);
        float2 vB = *(const float2*)(pB + col);
        xn[g * 4 + 0] = vA.x; xn[g * 4 + 1] = vA.y;
        xn[g * 4 + 2] = vB.x; xn[g * 4 + 3] = vB.y;
    }

    const u32 aoffb = (u32)(((l & 7) + ((l >> 3) & 1) * 8) * A_PITCH + (l >> 4) * 16);
    int buf = 0;
    __syncthreads();

    for (int t = 0; t < TSEQ; t++) {
        const u32 hbase = sb + RS_H + (u32)(buf * 4608);
        u32 ah[4][4], al[4][4];
#pragma unroll
        for (int ks = 0; ks < 4; ks++) {
            ldsm4(ah[ks], hbase + aoffb + ks * 32);
            ldsm4(al[ks], hbase + 2304 + aoffb + ks * 32);
        }

        float hh[16], lh[16], hl[16];
#pragma unroll
        for (int i = 0; i < 16; i++) { hh[i] = xn[i]; lh[i] = 0.f; hl[i] = 0.f; }

#pragma unroll
        for (int ks = 0; ks < 4; ks++) {
#pragma unroll
            for (int g = 0; g < 4; g++) {
                mma16816(&hh[g * 4], ah[ks], bh[g][ks]);
                mma16816(&lh[g * 4], al[ks], bh[g][ks]);
                mma16816(&hl[g * 4], ah[ks], bl[g][ks]);
            }
        }

        if (t + 1 < TSEQ) {
#pragma unroll
            for (int g = 0; g < 4; g++) {
                int col = 64 * g + u0;
                float2 vA = *(const float2*)(pA + (size_t)(t + 1) * NG + col);
                float2 vB = *(const float2*)(pB + (size_t)(t + 1) * NG + col);
                xn[g * 4 + 0] = vA.x; xn[g * 4 + 1] = vA.y;
                xn[g * 4 + 2] = vB.x; xn[g * 4 + 3] = vB.y;
            }
        }

        const u32 noff = RS_H + (u32)((buf ^ 1) * 4608);
#pragma unroll
        for (int r01 = 0; r01 < 2; r01++) {
            float hv[2];
#pragma unroll
            for (int e = 0; e < 2; e++) {
                int fi = r01 * 2 + e;
                float zi = hh[0 * 4 + fi] + lh[0 * 4 + fi] + hl[0 * 4 + fi];
                float zf = hh[1 * 4 + fi] + lh[1 * 4 + fi] + hl[1 * 4 + fi];
                float zg = hh[2 * 4 + fi] + lh[2 * 4 + fi] + hl[2 * 4 + fi];
                float zo = hh[3 * 4 + fi] + lh[3 * 4 + fi] + hl[3 * 4 + fi];
                float ig = sig_ap(zi);
                float fg = sig_ap(zf);
                float gg = (ACT == 0) ? tanh_ap(zg) : sig_ap(zg);
                float og = sig_ap(zo);
                int ci = r01 * 2 + e;
                c[ci] = fmaf(fg, c[ci], ig * gg);
                float ca = (ACT == 0) ? tanh_ap(c[ci]) : sig_ap(c[ci]);
                hv[e] = og * ca;
            }
            __nv_bfloat16 q0 = __float2bfloat16(hv[0]);
            __nv_bfloat16 q1 = __float2bfloat16(hv[1]);
            u32 hip = ((u32)__bfloat16_as_ushort(q1) << 16) | __bfloat16_as_ushort(q0);
            u32 lop = cvt2bf(hv[0] - __bfloat162float(q0),
                             hv[1] - __bfloat162float(q1));
            int row_s = r + 8 * r01;
            u32 hoff = (u32)(row_s * A_PITCH + u0 * 2);
            *(u32*)(smem + noff + hoff)        = hip;
            *(u32*)(smem + noff + 2304 + hoff) = lop;

            size_t o = ((size_t)(b0 + row_s) * TSEQ + t) * HU + u0;
            if (OUTBF) {
                *(u32*)(ohi + o) = hip;   // bf16 pair for units u0, u0+1
                *(u32*)(olo + o) = lop;
            } else {
                *(float2*)(hout + o) = make_float2(hv[0], hv[1]);
            }
        }
        __syncthreads();
        buf ^= 1;
    }
}

// ---------------------------------------------------------------------------
// Launch
// ---------------------------------------------------------------------------
extern "C" void kernel_launch(void* const* d_in, const int* in_sizes, int n_in,
                              void* d_out, int out_size)
{
    const float* x  = (const float*)d_in[0];
    const float* W1 = (const float*)d_in[1];
    const float* U1 = (const float*)d_in[2];
    const float* b1 = (const float*)d_in[3];
    const float* W2 = (const float*)d_in[4];
    const float* U2 = (const float*)d_in[5];
    const float* b2 = (const float*)d_in[6];
    float* out = (float*)d_out;

    void *xz_p, *ahi_p, *alo_p, *whi_p, *wlo_p;
    cudaGetSymbolAddress(&xz_p, g_xz);
    cudaGetSymbolAddress(&ahi_p, g_ahi);
    cudaGetSymbolAddress(&alo_p, g_alo);
    cudaGetSymbolAddress(&whi_p, g_whi);
    cudaGetSymbolAddress(&wlo_p, g_wlo);
    float* xz = (float*)xz_p;
    __nv_bfloat16* ahi = (__nv_bfloat16*)ahi_p;
    __nv_bfloat16* alo = (__nv_bfloat16*)alo_p;
    __nv_bfloat16* whi = (__nv_bfloat16*)whi_p;
    __nv_bfloat16* wlo = (__nv_bfloat16*)wlo_p;

    cudaFuncSetAttribute(gemm_tc_kernel<128>,
                         cudaFuncAttributeMaxDynamicSharedMemorySize, GEMM_SMEM);
    cudaFuncSetAttribute(gemm_tc_kernel<64>,
                         cudaFuncAttributeMaxDynamicSharedMemorySize, GEMM_SMEM);
    cudaFuncSetAttribute(lstm_rec_mma<0, 1>,
                         cudaFuncAttributeMaxDynamicSharedMemorySize, REC_SMEM);
    cudaFuncSetAttribute(lstm_rec_mma<1, 0>,
                         cudaFuncAttributeMaxDynamicSharedMemorySize, REC_SMEM);

    dim3 ggrid(MTOT / 128, 2);

    // Layer 1: convert x and W1 once, GEMM on pre-split inputs
    conv_split_kernel<<<4096, 256>>>(x, ahi, alo, MTOT * 128 / 4);
    conv_split_kernel<<<32, 256>>>(W1, whi, wlo, 128 * NG / 4);
    gemm_tc_kernel<128><<<ggrid, 256, GEMM_SMEM>>>(ahi, alo, whi, wlo, b1, xz);
    // rec<0> writes h1 straight into the split-A buffers for layer 2
    lstm_rec_mma<0, 1><<<BATCH / 16, 256, REC_SMEM>>>(xz, U1, out, ahi, alo);

    // Layer 2
    conv_split_kernel<<<32, 256>>>(W2, whi, wlo, 64 * NG / 4);
    gemm_tc_kernel<64><<<ggrid, 256, GEMM_SMEM>>>(ahi, alo, whi, wlo, b2, xz);
    lstm_rec_mma<1, 0><<<BATCH / 16, 256, REC_SMEM>>>(xz, U2, out, ahi, alo);
}

// round 14
// speedup vs baseline: 1.1775x; 1.1775x over previous
#include <cuda_runtime.h>
#include <cuda_bf16.h>
#include <math.h>

// Problem constants
#define TSEQ 128
#define HU   64
#define NG   256
#define BATCH 2048

typedef unsigned long long u64;
typedef unsigned int u32;

// Scratch: layer-1 hidden sequence as split bf16 (written by L1, read by L2)
__device__ __nv_bfloat16 g_h1hi[(size_t)BATCH * TSEQ * HU];
__device__ __nv_bfloat16 g_h1lo[(size_t)BATCH * TSEQ * HU];

// ---------------------------------------------------------------------------
// Activation helpers
// ---------------------------------------------------------------------------
__device__ __forceinline__ float tanh_ap(float x) {
    float y; asm("tanh.approx.f32 %0, %1;" : "=f"(y) : "f"(x)); return y;
}
__device__ __forceinline__ float sig_ap(float x) {
    return fmaf(0.5f, tanh_ap(0.5f * x), 0.5f);
}

// ---------------------------------------------------------------------------
// mma.sync / ldmatrix helpers
// ---------------------------------------------------------------------------
__device__ __forceinline__ u32 smem_u32(const void* p) {
    u32 a;
    asm("{ .reg .u64 t; cvta.to.shared.u64 t, %1; cvt.u32.u64 %0, t; }"
        : "=r"(a) : "l"(p));
    return a;
}
__device__ __forceinline__ void ldsm4(u32 r[4], u32 addr) {
    asm volatile("ldmatrix.sync.aligned.m8n8.x4.shared.b16 {%0,%1,%2,%3}, [%4];"
                 : "=r"(r[0]), "=r"(r[1]), "=r"(r[2]), "=r"(r[3]) : "r"(addr));
}
__device__ __forceinline__ void ldsm2t(u32 r[2], u32 addr) {
    asm volatile("ldmatrix.sync.aligned.m8n8.x2.trans.shared.b16 {%0,%1}, [%2];"
                 : "=r"(r[0]), "=r"(r[1]) : "r"(addr));
}
__device__ __forceinline__ void mma16816(float d[4], const u32 a[4], const u32 b[2]) {
    asm volatile(
        "mma.sync.aligned.m16n8k16.row.col.f32.bf16.bf16.f32 "
        "{%0,%1,%2,%3}, {%4,%5,%6,%7}, {%8,%9}, {%0,%1,%2,%3};"
        : "+f"(d[0]), "+f"(d[1]), "+f"(d[2]), "+f"(d[3])
        : "r"(a[0]), "r"(a[1]), "r"(a[2]), "r"(a[3]), "r"(b[0]), "r"(b[1]));
}
// pack two fp32 -> bf16x2 (first arg in lower half)
__device__ __forceinline__ u32 cvt2bf(float lo, float hi) {
    u32 r; asm("cvt.rn.bf16x2.f32 %0, %1, %2;" : "=r"(r) : "f"(hi), "f"(lo));
    return r;
}

// ---------------------------------------------------------------------------
// Fused LSTM layer kernel: per step t computes
//   z = bias + x(t) @ W + h(t-1) @ U      (split-fp32 bf16 HMMA, 3 terms)
// then gates/cell/h, all in one persistent per-batch-block loop.
// 128 blocks x TB=16 batch rows, 256 threads (8 warps).
// Warp w owns n-cols {8w..8w+7} + 64g — in-register gate epilogue.
//
// Smem: [0 .. 2*KIN*528)   W split (hi, lo)   (U staged here FIRST, then
//                           preloaded to regs and overwritten by W)
//       [SH .. SH+9216)     h double-buffer (hi 2304 + lo 2304 per buf)
//       [SX .. SX+2*XBUF)   x(t) double-buffer (hi + lo per buf, pitch XP)
//
// INBF: 0 = fp32 input (x), 1 = split-bf16 input (h1 from layer 1)
// OUTBF: 1 = write h as split bf16 (for next layer), 0 = write fp32 output
// ---------------------------------------------------------------------------
template <int ACT, int KIN, int INBF, int OUTBF>
__global__ __launch_bounds__(256, 1) void lstm_fused(
    const float* __restrict__ Xf,
    const float* __restrict__ W, const float* __restrict__ U,
    const float* __restrict__ bias,
    float* __restrict__ outf,
    __nv_bfloat16* __restrict__ ohi, __nv_bfloat16* __restrict__ olo,
    const __nv_bfloat16* __restrict__ inhi, const __nv_bfloat16* __restrict__ inlo)
{
    extern __shared__ char smem[];
    const u32 sb = smem_u32(smem);

    constexpr int XP    = (KIN == 128) ? 272 : 144;  // x-tile pitch (conflict-free)
    constexpr int SWLO  = KIN * 528;                 // W lo half
    constexpr int SH    = 2 * KIN * 528;             // h buffers
    constexpr int SX    = SH + 9216;                 // x buffers
    constexpr int XTERM = 16 * XP;                   // one term of one x buf
    constexpr int XBUF  = 2 * XTERM;                 // hi+lo per x buf
    constexpr int NXKS  = KIN / 16;                  // x k16 steps

    const int tid = threadIdx.x;
    const int w   = tid >> 5;
    const int l   = tid & 31;
    const int b0  = blockIdx.x * 16;

    // ================= Phase A: stage U, preload U b-fragments ==============
#pragma unroll
    for (int i = 0; i < 16; i++) {
        int idx = tid + i * 256;            // 4096 float4 = 64x256 floats
        int k = idx >> 6, nq = idx & 63;
        float4 v = *(const float4*)(U + (size_t)k * NG + nq * 4);
        __nv_bfloat16 h0 = __float2bfloat16(v.x);
        __nv_bfloat16 h1 = __float2bfloat16(v.y);
        __nv_bfloat16 h2 = __float2bfloat16(v.z);
        __nv_bfloat16 h3 = __float2bfloat16(v.w);
        u32 hp0 = ((u32)__bfloat16_as_ushort(h1) << 16) | __bfloat16_as_ushort(h0);
        u32 hp1 = ((u32)__bfloat16_as_ushort(h3) << 16) | __bfloat16_as_ushort(h2);
        u32 lp0 = cvt2bf(v.x - __bfloat162float(h0), v.y - __bfloat162float(h1));
        u32 lp1 = cvt2bf(v.z - __bfloat162float(h2), v.w - __bfloat162float(h3));
        u32 off = (u32)(k * 528 + nq * 8);
        *(u64*)(smem + off)         = ((u64)hp1 << 32) | hp0;
        *(u64*)(smem + 33792 + off) = ((u64)lp1 << 32) | lp0;
    }
    __syncthreads();

    u32 bh[4][4][2], bl[4][4][2];           // U b-frags [gate][ks][2]
    const u32 brow = (u32)((l & 7) + ((l >> 3) & 1) * 8);
#pragma unroll
    for (int g = 0; g < 4; g++)
#pragma unroll
        for (int ks = 0; ks < 4; ks++) {
            u32 off = (ks * 16 + brow) * 528 + (u32)(64 * g + 8 * w) * 2;
            ldsm2t(bh[g][ks], sb + off);
            ldsm2t(bl[g][ks], sb + 33792 + off);
        }
    __syncthreads();   // all warps done reading U region before W overwrites it

    // ================= Phase B: stage W, zero h bufs, stage x(0) ============
#pragma unroll
    for (int i = 0; i < KIN / 4; i++) {     // KIN*64 float4 total
        int idx = tid + i * 256;
        int k = idx >> 6, nq = idx & 63;
        float4 v = *(const float4*)(W + (size_t)k * NG + nq * 4);
        __nv_bfloat16 h0 = __float2bfloat16(v.x);
        __nv_bfloat16 h1 = __float2bfloat16(v.y);
        __nv_bfloat16 h2 = __float2bfloat16(v.z);
        __nv_bfloat16 h3 = __float2bfloat16(v.w);
        u32 hp0 = ((u32)__bfloat16_as_ushort(h1) << 16) | __bfloat16_as_ushort(h0);
        u32 hp1 = ((u32)__bfloat16_as_ushort(h3) << 16) | __bfloat16_as_ushort(h2);
        u32 lp0 = cvt2bf(v.x - __bfloat162float(h0), v.y - __bfloat162float(h1));
        u32 lp1 = cvt2bf(v.z - __bfloat162float(h2), v.w - __bfloat162float(h3));
        u32 off = (u32)(k * 528 + nq * 8);
        *(u64*)(smem + off)        = ((u64)hp1 << 32) | hp0;
        *(u64*)(smem + SWLO + off) = ((u64)lp1 << 32) | lp0;
    }
    // zero both h buffers (9216 B)
#pragma unroll
    for (int i = 0; i < 9; i++)
        *(u32*)(smem + SH + (u32)(tid + i * 256) * 4) = 0;

    // stage x(0) into x buf 0
    {
        int row = tid >> 4, q = tid & 15;
        if (INBF) {
            size_t so = ((size_t)(b0 + row) * TSEQ + 0) * HU + q * 4;
            *(u64*)(smem + SX + row * XP + q * 8)         = *(const u64*)(inhi + so);
            *(u64*)(smem + SX + XTERM + row * XP + q * 8) = *(const u64*)(inlo + so);
        } else {
            const float* s = Xf + ((size_t)(b0 + row) * TSEQ + 0) * KIN + q * 8;
            float4 v0 = *(const float4*)s;
            float4 v1 = *(const float4*)(s + 4);
            __nv_bfloat16 a0 = __float2bfloat16(v0.x), a1 = __float2bfloat16(v0.y);
            __nv_bfloat16 a2 = __float2bfloat16(v0.z), a3 = __float2bfloat16(v0.w);
            __nv_bfloat16 a4 = __float2bfloat16(v1.x), a5 = __float2bfloat16(v1.y);
            __nv_bfloat16 a6 = __float2bfloat16(v1.z), a7 = __float2bfloat16(v1.w);
            uint4 hi4, lo4;
            hi4.x = ((u32)__bfloat16_as_ushort(a1) << 16) | __bfloat16_as_ushort(a0);
            hi4.y = ((u32)__bfloat16_as_ushort(a3) << 16) | __bfloat16_as_ushort(a2);
            hi4.z = ((u32)__bfloat16_as_ushort(a5) << 16) | __bfloat16_as_ushort(a4);
            hi4.w = ((u32)__bfloat16_as_ushort(a7) << 16) | __bfloat16_as_ushort(a6);
            lo4.x = cvt2bf(v0.x - __bfloat162float(a0), v0.y - __bfloat162float(a1));
            lo4.y = cvt2bf(v0.z - __bfloat162float(a2), v0.w - __bfloat162float(a3));
            lo4.z = cvt2bf(v1.x - __bfloat162float(a4), v1.y - __bfloat162float(a5));
            lo4.w = cvt2bf(v1.z - __bfloat162float(a6), v1.w - __bfloat162float(a7));
            *(uint4*)(smem + SX + row * XP + q * 16)         = hi4;
            *(uint4*)(smem + SX + XTERM + row * XP + q * 16) = lo4;
        }
    }
    __syncthreads();

    // ================= Main loop ===========================================
    const u32 aoffh = brow * 144 + (u32)(l >> 4) * 16;
    const u32 aoffx = brow * XP  + (u32)(l >> 4) * 16;
    const u32 boffW = brow * 528 + (u32)(8 * w) * 2;
    const int r   = l >> 2;
    const int cq2 = 2 * (l & 3);
    const int u0  = 8 * w + cq2;

    float bseed[8];
#pragma unroll
    for (int g = 0; g < 4; g++) {
        bseed[g * 2 + 0] = bias[64 * g + u0];
        bseed[g * 2 + 1] = bias[64 * g + u0 + 1];
    }
    float c[4];
#pragma unroll
    for (int i = 0; i < 4; i++) c[i] = 0.f;

    for (int t = 0; t < TSEQ; t++) {
        const u32 hbase = sb + SH + (u32)((t & 1) * 4608);
        const u32 xbase = sb + SX + (u32)((t & 1) * XBUF);

        // hoist h fragments
        u32 ah[4][4], al_[4][4];
#pragma unroll
        for (int ks = 0; ks < 4; ks++) {
            ldsm4(ah[ks],  hbase + aoffh + ks * 32);
            ldsm4(al_[ks], hbase + 2304 + aoffh + ks * 32);
        }

        // three independent accumulator chains; hh seeded with bias
        float hh[16], lh[16], hl[16];
#pragma unroll
        for (int i = 0; i < 16; i++) {
            hh[i] = bseed[(i >> 2) * 2 + (i & 1)];
            lh[i] = 0.f; hl[i] = 0.f;
        }

        // h(t-1) @ U
#pragma unroll
        for (int ks = 0; ks < 4; ks++)
#pragma unroll
            for (int g = 0; g < 4; g++) {
                mma16816(&hh[g * 4], ah[ks],  bh[g][ks]);
                mma16816(&lh[g * 4], al_[ks], bh[g][ks]);
                mma16816(&hl[g * 4], ah[ks],  bl[g][ks]);
            }

        // x(t) @ W
#pragma unroll
        for (int xks = 0; xks < NXKS; xks++) {
            u32 xah[4], xal[4];
            ldsm4(xah, xbase + aoffx + xks * 32);
            ldsm4(xal, xbase + XTERM + aoffx + xks * 32);
#pragma unroll
            for (int g = 0; g < 4; g++) {
                u32 wh[2], wl[2];
                ldsm2t(wh, sb + boffW + (u32)(xks * 16 * 528) + (u32)(g * 128));
                ldsm2t(wl, sb + SWLO + boffW + (u32)(xks * 16 * 528) + (u32)(g * 128));
                mma16816(&hh[g * 4], xah, wh);
                mma16816(&lh[g * 4], xal, wh);
                mma16816(&hl[g * 4], xah, wl);
            }
        }

        // stage x(t+1) into the other buffer (overlaps MMA drain)
        if (t + 1 < TSEQ) {
            u32 nxb = sb + SX + (u32)(((t + 1) & 1) * XBUF);
            int row = tid >> 4, q = tid & 15;
            if (INBF) {
                size_t so = ((size_t)(b0 + row) * TSEQ + (t + 1)) * HU + q * 4;
                *(u64*)((char*)smem + (nxb - sb) + row * XP + q * 8) =
                    *(const u64*)(inhi + so);
                *(u64*)((char*)smem + (nxb - sb) + XTERM + row * XP + q * 8) =
                    *(const u64*)(inlo + so);
            } else {
                const float* s = Xf + ((size_t)(b0 + row) * TSEQ + (t + 1)) * KIN + q * 8;
                float4 v0 = *(const float4*)s;
                float4 v1 = *(const float4*)(s + 4);
                __nv_bfloat16 a0 = __float2bfloat16(v0.x), a1 = __float2bfloat16(v0.y);
                __nv_bfloat16 a2 = __float2bfloat16(v0.z), a3 = __float2bfloat16(v0.w);
                __nv_bfloat16 a4 = __float2bfloat16(v1.x), a5 = __float2bfloat16(v1.y);
                __nv_bfloat16 a6 = __float2bfloat16(v1.z), a7 = __float2bfloat16(v1.w);
                uint4 hi4, lo4;
                hi4.x = ((u32)__bfloat16_as_ushort(a1) << 16) | __bfloat16_as_ushort(a0);
                hi4.y = ((u32)__bfloat16_as_ushort(a3) << 16) | __bfloat16_as_ushort(a2);
                hi4.z = ((u32)__bfloat16_as_ushort(a5) << 16) | __bfloat16_as_ushort(a4);
                hi4.w = ((u32)__bfloat16_as_ushort(a7) << 16) | __bfloat16_as_ushort(a6);
                lo4.x = cvt2bf(v0.x - __bfloat162float(a0), v0.y - __bfloat162float(a1));
                lo4.y = cvt2bf(v0.z - __bfloat162float(a2), v0.w - __bfloat162float(a3));
                lo4.z = cvt2bf(v1.x - __bfloat162float(a4), v1.y - __bfloat162float(a5));
                lo4.w = cvt2bf(v1.z - __bfloat162float(a6), v1.w - __bfloat162float(a7));
                *(uint4*)((char*)smem + (nxb - sb) + row * XP + q * 16)         = hi4;
                *(uint4*)((char*)smem + (nxb - sb) + XTERM + row * XP + q * 16) = lo4;
            }
        }

        // gates + h writeback
        const u32 noff = SH + (u32)(((t + 1) & 1) * 4608);
#pragma unroll
        for (int r01 = 0; r01 < 2; r01++) {
            float hv[2];
#pragma unroll
            for (int e = 0; e < 2; e++) {
                int fi = r01 * 2 + e;
                float zi = hh[0 * 4 + fi] + lh[0 * 4 + fi] + hl[0 * 4 + fi];
                float zf = hh[1 * 4 + fi] + lh[1 * 4 + fi] + hl[1 * 4 + fi];
                float zg = hh[2 * 4 + fi] + lh[2 * 4 + fi] + hl[2 * 4 + fi];
                float zo = hh[3 * 4 + fi] + lh[3 * 4 + fi] + hl[3 * 4 + fi];
                float ig = sig_ap(zi);
                float fg = sig_ap(zf);
                float gg = (ACT == 0) ? tanh_ap(zg) : sig_ap(zg);
                float og = sig_ap(zo);
                int ci = r01 * 2 + e;
                c[ci] = fmaf(fg, c[ci], ig * gg);
                float ca = (ACT == 0) ? tanh_ap(c[ci]) : sig_ap(c[ci]);
                hv[e] = og * ca;
            }
            __nv_bfloat16 q0 = __float2bfloat16(hv[0]);
            __nv_bfloat16 q1 = __float2bfloat16(hv[1]);
            u32 hip = ((u32)__bfloat16_as_ushort(q1) << 16) | __bfloat16_as_ushort(q0);
            u32 lop = cvt2bf(hv[0] - __bfloat162float(q0),
                             hv[1] - __bfloat162float(q1));
            int row_s = r + 8 * r01;
            u32 hoff = (u32)(row_s * 144 + u0 * 2);
            *(u32*)(smem + noff + hoff)        = hip;
            *(u32*)(smem + noff + 2304 + hoff) = lop;

            size_t o = ((size_t)(b0 + row_s) * TSEQ + t) * HU + u0;
            if (OUTBF) {
                *(u32*)(ohi + o) = hip;
                *(u32*)(olo + o) = lop;
            } else {
                *(float2*)(outf + o) = make_float2(hv[0], hv[1]);
            }
        }
        __syncthreads();
    }
}

// Smem sizes
#define SM_L1 (2 * 128 * 528 + 9216 + 2 * (2 * 16 * 272))   // 161792
#define SM_L2 (2 * 64 * 528 + 9216 + 2 * (2 * 16 * 144))    // 86016

// ---------------------------------------------------------------------------
// Launch
// ---------------------------------------------------------------------------
extern "C" void kernel_launch(void* const* d_in, const int* in_sizes, int n_in,
                              void* d_out, int out_size)
{
    const float* x  = (const float*)d_in[0];
    const float* W1 = (const float*)d_in[1];
    const float* U1 = (const float*)d_in[2];
    const float* b1 = (const float*)d_in[3];
    const float* W2 = (const float*)d_in[4];
    const float* U2 = (const float*)d_in[5];
    const float* b2 = (const float*)d_in[6];
    float* out = (float*)d_out;

    void *hhi_p, *hlo_p;
    cudaGetSymbolAddress(&hhi_p, g_h1hi);
    cudaGetSymbolAddress(&hlo_p, g_h1lo);
    __nv_bfloat16* h1hi = (__nv_bfloat16*)hhi_p;
    __nv_bfloat16* h1lo = (__nv_bfloat16*)hlo_p;

    cudaFuncSetAttribute((const void*)lstm_fused<0, 128, 0, 1>,
                         cudaFuncAttributeMaxDynamicSharedMemorySize, SM_L1);
    cudaFuncSetAttribute((const void*)lstm_fused<1, 64, 1, 0>,
                         cudaFuncAttributeMaxDynamicSharedMemorySize, SM_L2);

    // Layer 1: x -> h1 (split bf16)
    lstm_fused<0, 128, 0, 1><<<BATCH / 16, 256, SM_L1>>>(
        x, W1, U1, b1, out, h1hi, h1lo, nullptr, nullptr);

    // Layer 2: h1 -> out (fp32, layout == required reshape)
    lstm_fused<1, 64, 1, 0><<<BATCH / 16, 256, SM_L2>>>(
        nullptr, W2, U2, b2, out, nullptr, nullptr, h1hi, h1lo);
}

// round 16
// speedup vs baseline: 1.3304x; 1.1298x over previous
#include <cuda_runtime.h>
#include <cuda_bf16.h>
#include <math.h>

// Problem constants
#define TSEQ 128
#define HU   64
#define NG   256
#define BATCH 2048

typedef unsigned long long u64;
typedef unsigned int u32;

// Scratch: layer-1 hidden sequence as split bf16 (written by L1, read by L2)
__device__ __nv_bfloat16 g_h1hi[(size_t)BATCH * TSEQ * HU];
__device__ __nv_bfloat16 g_h1lo[(size_t)BATCH * TSEQ * HU];

// ---------------------------------------------------------------------------
// Activation helpers
// ---------------------------------------------------------------------------
__device__ __forceinline__ float tanh_ap(float x) {
    float y; asm("tanh.approx.f32 %0, %1;" : "=f"(y) : "f"(x)); return y;
}
__device__ __forceinline__ float sig_ap(float x) {
    return fmaf(0.5f, tanh_ap(0.5f * x), 0.5f);
}

// ---------------------------------------------------------------------------
// mma.sync / ldmatrix helpers
// ---------------------------------------------------------------------------
__device__ __forceinline__ u32 smem_u32(const void* p) {
    u32 a;
    asm("{ .reg .u64 t; cvta.to.shared.u64 t, %1; cvt.u32.u64 %0, t; }"
        : "=r"(a) : "l"(p));
    return a;
}
__device__ __forceinline__ void ldsm4(u32 r[4], u32 addr) {
    asm volatile("ldmatrix.sync.aligned.m8n8.x4.shared.b16 {%0,%1,%2,%3}, [%4];"
                 : "=r"(r[0]), "=r"(r[1]), "=r"(r[2]), "=r"(r[3]) : "r"(addr));
}
__device__ __forceinline__ void ldsm2t(u32 r[2], u32 addr) {
    asm volatile("ldmatrix.sync.aligned.m8n8.x2.trans.shared.b16 {%0,%1}, [%2];"
                 : "=r"(r[0]), "=r"(r[1]) : "r"(addr));
}
__device__ __forceinline__ void mma16816(float d[4], const u32 a[4], const u32 b[2]) {
    asm volatile(
        "mma.sync.aligned.m16n8k16.row.col.f32.bf16.bf16.f32 "
        "{%0,%1,%2,%3}, {%4,%5,%6,%7}, {%8,%9}, {%0,%1,%2,%3};"
        : "+f"(d[0]), "+f"(d[1]), "+f"(d[2]), "+f"(d[3])
        : "r"(a[0]), "r"(a[1]), "r"(a[2]), "r"(a[3]), "r"(b[0]), "r"(b[1]));
}
// pack two fp32 -> bf16x2 (first arg in lower half)
__device__ __forceinline__ u32 cvt2bf(float lo, float hi) {
    u32 r; asm("cvt.rn.bf16x2.f32 %0, %1, %2;" : "=r"(r) : "f"(hi), "f"(lo));
    return r;
}

// ---------------------------------------------------------------------------
// Fused + pipelined LSTM layer kernel.
// Per step t: (A) U MMAs finish CUR z-chains; (D) x(t+1)@W MMAs build NXT
// chains (independent of h(t) -> fills tensor pipe during epilogue);
// (B) gates/cell/h epilogue + writeback; 1 barrier.
// x staged TWO steps ahead in a double buffer. 2-step unroll (ping-pong regs).
// 128 blocks x TB=16 rows, 256 threads (8 warps), warp w owns n-cols
// {8w..8w+7}+64g (in-register gates).
// INBF: 0 = fp32 input, 1 = split-bf16 input. OUTBF: 1 = split-bf16 out.
// ---------------------------------------------------------------------------
template <int ACT, int KIN, int INBF, int OUTBF>
__global__ __launch_bounds__(256, 1) void lstm_fused(
    const float* __restrict__ Xf,
    const float* __restrict__ W, const float* __restrict__ U,
    const float* __restrict__ bias,
    float* __restrict__ outf,
    __nv_bfloat16* __restrict__ ohi, __nv_bfloat16* __restrict__ olo,
    const __nv_bfloat16* __restrict__ inhi, const __nv_bfloat16* __restrict__ inlo)
{
    extern __shared__ char smem[];
    const u32 sb = smem_u32(smem);

    constexpr int XP    = (KIN == 128) ? 272 : 144;
    constexpr int SWLO  = KIN * 528;
    constexpr int SH    = 2 * KIN * 528;
    constexpr int SX    = SH + 9216;
    constexpr int XTERM = 16 * XP;
    constexpr int XBUF  = 2 * XTERM;
    constexpr int NXKS  = KIN / 16;

    const int tid = threadIdx.x;
    const int w   = tid >> 5;
    const int l   = tid & 31;
    const int b0  = blockIdx.x * 16;

    // ===== Phase A: stage U, preload U b-fragments =====
#pragma unroll
    for (int i = 0; i < 16; i++) {
        int idx = tid + i * 256;
        int k = idx >> 6, nq = idx & 63;
        float4 v = *(const float4*)(U + (size_t)k * NG + nq * 4);
        __nv_bfloat16 h0 = __float2bfloat16(v.x);
        __nv_bfloat16 h1 = __float2bfloat16(v.y);
        __nv_bfloat16 h2 = __float2bfloat16(v.z);
        __nv_bfloat16 h3 = __float2bfloat16(v.w);
        u32 hp0 = ((u32)__bfloat16_as_ushort(h1) << 16) | __bfloat16_as_ushort(h0);
        u32 hp1 = ((u32)__bfloat16_as_ushort(h3) << 16) | __bfloat16_as_ushort(h2);
        u32 lp0 = cvt2bf(v.x - __bfloat162float(h0), v.y - __bfloat162float(h1));
        u32 lp1 = cvt2bf(v.z - __bfloat162float(h2), v.w - __bfloat162float(h3));
        u32 off = (u32)(k * 528 + nq * 8);
        *(u64*)(smem + off)         = ((u64)hp1 << 32) | hp0;
        *(u64*)(smem + 33792 + off) = ((u64)lp1 << 32) | lp0;
    }
    __syncthreads();

    u32 bh[4][4][2], bl[4][4][2];
    const u32 brow = (u32)((l & 7) + ((l >> 3) & 1) * 8);
#pragma unroll
    for (int g = 0; g < 4; g++)
#pragma unroll
        for (int ks = 0; ks < 4; ks++) {
            u32 off = (ks * 16 + brow) * 528 + (u32)(64 * g + 8 * w) * 2;
            ldsm2t(bh[g][ks], sb + off);
            ldsm2t(bl[g][ks], sb + 33792 + off);
        }
    __syncthreads();

    // ===== Phase B: stage W =====
#pragma unroll
    for (int i = 0; i < KIN / 4; i++) {
        int idx = tid + i * 256;
        int k = idx >> 6, nq = idx & 63;
        float4 v = *(const float4*)(W + (size_t)k * NG + nq * 4);
        __nv_bfloat16 h0 = __float2bfloat16(v.x);
        __nv_bfloat16 h1 = __float2bfloat16(v.y);
        __nv_bfloat16 h2 = __float2bfloat16(v.z);
        __nv_bfloat16 h3 = __float2bfloat16(v.w);
        u32 hp0 = ((u32)__bfloat16_as_ushort(h1) << 16) | __bfloat16_as_ushort(h0);
        u32 hp1 = ((u32)__bfloat16_as_ushort(h3) << 16) | __bfloat16_as_ushort(h2);
        u32 lp0 = cvt2bf(v.x - __bfloat162float(h0), v.y - __bfloat162float(h1));
        u32 lp1 = cvt2bf(v.z - __bfloat162float(h2), v.w - __bfloat162float(h3));
        u32 off = (u32)(k * 528 + nq * 8);
        *(u64*)(smem + off)        = ((u64)hp1 << 32) | hp0;
        *(u64*)(smem + SWLO + off) = ((u64)lp1 << 32) | lp0;
    }
    // zero both h buffers
#pragma unroll
    for (int i = 0; i < 9; i++)
        *(u32*)(smem + SH + (u32)(tid + i * 256) * 4) = 0;

    const int srow = tid >> 4, sq = tid & 15;

    // STAGE_X(tt, bufidx): stage x(tt) into x buffer bufidx
#define STAGE_X(tt, bufidx)                                                   \
    {                                                                         \
        u32 xb_ = (u32)(SX + (bufidx) * XBUF);                                \
        if (INBF) {                                                           \
            size_t so = ((size_t)(b0 + srow) * TSEQ + (tt)) * HU + sq * 4;    \
            *(u64*)(smem + xb_ + srow * XP + sq * 8) = *(const u64*)(inhi + so); \
            *(u64*)(smem + xb_ + XTERM + srow * XP + sq * 8) = *(const u64*)(inlo + so); \
        } else {                                                              \
            const float* s = Xf + ((size_t)(b0 + srow) * TSEQ + (tt)) * KIN + sq * 8; \
            float4 v0 = *(const float4*)s;                                    \
            float4 v1 = *(const float4*)(s + 4);                              \
            __nv_bfloat16 a0 = __float2bfloat16(v0.x), a1 = __float2bfloat16(v0.y); \
            __nv_bfloat16 a2 = __float2bfloat16(v0.z), a3 = __float2bfloat16(v0.w); \
            __nv_bfloat16 a4 = __float2bfloat16(v1.x), a5 = __float2bfloat16(v1.y); \
            __nv_bfloat16 a6 = __float2bfloat16(v1.z), a7 = __float2bfloat16(v1.w); \
            uint4 hi4, lo4;                                                   \
            hi4.x = ((u32)__bfloat16_as_ushort(a1) << 16) | __bfloat16_as_ushort(a0); \
            hi4.y = ((u32)__bfloat16_as_ushort(a3) << 16) | __bfloat16_as_ushort(a2); \
            hi4.z = ((u32)__bfloat16_as_ushort(a5) << 16) | __bfloat16_as_ushort(a4); \
            hi4.w = ((u32)__bfloat16_as_ushort(a7) << 16) | __bfloat16_as_ushort(a6); \
            lo4.x = cvt2bf(v0.x - __bfloat162float(a0), v0.y - __bfloat162float(a1)); \
            lo4.y = cvt2bf(v0.z - __bfloat162float(a2), v0.w - __bfloat162float(a3)); \
            lo4.z = cvt2bf(v1.x - __bfloat162float(a4), v1.y - __bfloat162float(a5)); \
            lo4.w = cvt2bf(v1.z - __bfloat162float(a6), v1.w - __bfloat162float(a7)); \
            *(uint4*)(smem + xb_ + srow * XP + sq * 16) = hi4;                \
            *(uint4*)(smem + xb_ + XTERM + srow * XP + sq * 16) = lo4;        \
        }                                                                     \
    }

    STAGE_X(0, 0)
    STAGE_X(1, 1)
    __syncthreads();

    // ===== Main loop setup =====
    const u32 aoffh = brow * 144 + (u32)(l >> 4) * 16;
    const u32 aoffx = brow * XP  + (u32)(l >> 4) * 16;
    const u32 boffW = brow * 528 + (u32)(8 * w) * 2;
    const int r   = l >> 2;
    const int cq2 = 2 * (l & 3);
    const int u0  = 8 * w + cq2;

    float bseed[8];
#pragma unroll
    for (int g = 0; g < 4; g++) {
        bseed[g * 2 + 0] = bias[64 * g + u0];
        bseed[g * 2 + 1] = bias[64 * g + u0 + 1];
    }
    float c[4];
#pragma unroll
    for (int i = 0; i < 4; i++) c[i] = 0.f;

    float accA[3][16], accB[3][16];

    // BUILD_XW(ACC, tt): ACC = bias + x(tt)@W  (3 split chains)
#define BUILD_XW(ACC, tt)                                                     \
    {                                                                         \
        _Pragma("unroll")                                                     \
        for (int i = 0; i < 16; i++) {                                        \
            ACC[0][i] = bseed[(i >> 2) * 2 + (i & 1)];                        \
            ACC[1][i] = 0.f; ACC[2][i] = 0.f;                                 \
        }                                                                     \
        const u32 xbase_ = sb + SX + (u32)(((tt) & 1) * XBUF);                \
        _Pragma("unroll")                                                     \
        for (int xks = 0; xks < NXKS; xks++) {                                \
            u32 xah[4], xal[4];                                               \
            ldsm4(xah, xbase_ + aoffx + xks * 32);                            \
            ldsm4(xal, xbase_ + XTERM + aoffx + xks * 32);                    \
            _Pragma("unroll")                                                 \
            for (int g = 0; g < 4; g++) {                                     \
                u32 wh[2], wl[2];                                             \
                ldsm2t(wh, sb + boffW + (u32)(xks * 16 * 528) + (u32)(g * 128)); \
                ldsm2t(wl, sb + SWLO + boffW + (u32)(xks * 16 * 528) + (u32)(g * 128)); \
                mma16816(&ACC[0][g * 4], xah, wh);                            \
                mma16816(&ACC[1][g * 4], xal, wh);                            \
                mma16816(&ACC[2][g * 4], xah, wl);                            \
            }                                                                 \
        }                                                                     \
    }

    // LSTM_STEP(t, CUR, NXT): full pipelined step
#define LSTM_STEP(t, CUR, NXT)                                                \
    {                                                                         \
        const u32 hbase_ = sb + SH + (u32)(((t) & 1) * 4608);                 \
        u32 ah_[4][4], al2_[4][4];                                            \
        _Pragma("unroll")                                                     \
        for (int ks = 0; ks < 4; ks++) {                                      \
            ldsm4(ah_[ks],  hbase_ + aoffh + ks * 32);                        \
            ldsm4(al2_[ks], hbase_ + 2304 + aoffh + ks * 32);                 \
        }                                                                     \
        _Pragma("unroll")                                                     \
        for (int ks = 0; ks < 4; ks++)                                        \
            _Pragma("unroll")                                                 \
            for (int g = 0; g < 4; g++) {                                     \
                mma16816(&CUR[0][g * 4], ah_[ks],  bh[g][ks]);                \
                mma16816(&CUR[1][g * 4], al2_[ks], bh[g][ks]);                \
                mma16816(&CUR[2][g * 4], ah_[ks],  bl[g][ks]);                \
            }                                                                 \
        if ((t) + 1 < TSEQ) { BUILD_XW(NXT, (t) + 1) }                        \
        if ((t) + 2 < TSEQ) { STAGE_X((t) + 2, (t) & 1) }                     \
        const u32 noff_ = SH + (u32)((((t) + 1) & 1) * 4608);                 \
        _Pragma("unroll")                                                     \
        for (int r01 = 0; r01 < 2; r01++) {                                   \
            float hv[2];                                                      \
            _Pragma("unroll")                                                 \
            for (int e = 0; e < 2; e++) {                                     \
                int fi = r01 * 2 + e;                                         \
                float zi = CUR[0][0 * 4 + fi] + CUR[1][0 * 4 + fi] + CUR[2][0 * 4 + fi]; \
                float zf = CUR[0][1 * 4 + fi] + CUR[1][1 * 4 + fi] + CUR[2][1 * 4 + fi]; \
                float zg = CUR[0][2 * 4 + fi] + CUR[1][2 * 4 + fi] + CUR[2][2 * 4 + fi]; \
                float zo = CUR[0][3 * 4 + fi] + CUR[1][3 * 4 + fi] + CUR[2][3 * 4 + fi]; \
                float ig = sig_ap(zi);                                        \
                float fg = sig_ap(zf);                                        \
                float gg = (ACT == 0) ? tanh_ap(zg) : sig_ap(zg);             \
                float og = sig_ap(zo);                                        \
                int ci = r01 * 2 + e;                                         \
                c[ci] = fmaf(fg, c[ci], ig * gg);                             \
                float ca = (ACT == 0) ? tanh_ap(c[ci]) : sig_ap(c[ci]);       \
                hv[e] = og * ca;                                              \
            }                                                                 \
            __nv_bfloat16 q0 = __float2bfloat16(hv[0]);                       \
            __nv_bfloat16 q1 = __float2bfloat16(hv[1]);                       \
            u32 hip = ((u32)__bfloat16_as_ushort(q1) << 16) | __bfloat16_as_ushort(q0); \
            u32 lop = cvt2bf(hv[0] - __bfloat162float(q0),                    \
                             hv[1] - __bfloat162float(q1));                   \
            int row_s = r + 8 * r01;                                          \
            u32 hoff = (u32)(row_s * 144 + u0 * 2);                           \
            *(u32*)(smem + noff_ + hoff)        = hip;                        \
            *(u32*)(smem + noff_ + 2304 + hoff) = lop;                        \
            size_t o = ((size_t)(b0 + row_s) * TSEQ + (t)) * HU + u0;         \
            if (OUTBF) {                                                      \
                *(u32*)(ohi + o) = hip;                                       \
                *(u32*)(olo + o) = lop;                                       \
            } else {                                                          \
                *(float2*)(outf + o) = make_float2(hv[0], hv[1]);             \
            }                                                                 \
        }                                                                     \
        __syncthreads();                                                      \
    }

    // Prologue: accA = bias + x(0)@W
    BUILD_XW(accA, 0)

    // 2-step unrolled main loop (ping-pong accumulator sets)
    for (int t2 = 0; t2 < TSEQ / 2; t2++) {
        int t = 2 * t2;
        LSTM_STEP(t,     accA, accB)
        LSTM_STEP(t + 1, accB, accA)
    }

#undef LSTM_STEP
#undef BUILD_XW
#undef STAGE_X
}

// Smem sizes
#define SM_L1 (2 * 128 * 528 + 9216 + 2 * (2 * 16 * 272))   // 161792
#define SM_L2 (2 * 64 * 528 + 9216 + 2 * (2 * 16 * 144))    // 86016

// ---------------------------------------------------------------------------
// Launch
// ---------------------------------------------------------------------------
extern "C" void kernel_launch(void* const* d_in, const int* in_sizes, int n_in,
                              void* d_out, int out_size)
{
    const float* x  = (const float*)d_in[0];
    const float* W1 = (const float*)d_in[1];
    const float* U1 = (const float*)d_in[2];
    const float* b1 = (const float*)d_in[3];
    const float* W2 = (const float*)d_in[4];
    const float* U2 = (const float*)d_in[5];
    const float* b2 = (const float*)d_in[6];
    float* out = (float*)d_out;

    void *hhi_p, *hlo_p;
    cudaGetSymbolAddress(&hhi_p, g_h1hi);
    cudaGetSymbolAddress(&hlo_p, g_h1lo);
    __nv_bfloat16* h1hi = (__nv_bfloat16*)hhi_p;
    __nv_bfloat16* h1lo = (__nv_bfloat16*)hlo_p;

    cudaFuncSetAttribute((const void*)lstm_fused<0, 128, 0, 1>,
                         cudaFuncAttributeMaxDynamicSharedMemorySize, SM_L1);
    cudaFuncSetAttribute((const void*)lstm_fused<1, 64, 1, 0>,
                         cudaFuncAttributeMaxDynamicSharedMemorySize, SM_L2);

    // Layer 1: x -> h1 (split bf16)
    lstm_fused<0, 128, 0, 1><<<BATCH / 16, 256, SM_L1>>>(
        x, W1, U1, b1, out, h1hi, h1lo, nullptr, nullptr);

    // Layer 2: h1 -> out (fp32, layout == required reshape)
    lstm_fused<1, 64, 1, 0><<<BATCH / 16, 256, SM_L2>>>(
        nullptr, W2, U2, b2, out, nullptr, nullptr, h1hi, h1lo);
}